// round 14
// baseline (speedup 1.0000x reference)
#include <cuda_runtime.h>
#include <cuda_fp16.h>
#include <cstdint>

#define BATCH   4
#define S_LEN   2048
#define DM      1024
#define NH      16
#define DK      64
#define M_TOT   (BATCH * S_LEN)   // 8192

// ---------------------------------------------------------------------------
// Scratch (device globals; no dynamic allocation allowed)
// ---------------------------------------------------------------------------
__device__ __half g_Xh[(size_t)M_TOT * DM];
__device__ __half g_Wq[(size_t)DM * DM];
__device__ __half g_Wk[(size_t)DM * DM];
__device__ __half g_Wv[(size_t)DM * DM];
__device__ __half g_Wo[(size_t)DM * DM];
__device__ __half g_Q[(size_t)BATCH * NH * S_LEN * DK];   // [bh, s, d] (scaled by 0.125*log2e)
__device__ __half g_K[(size_t)BATCH * NH * S_LEN * DK];
__device__ __half g_V[(size_t)BATCH * NH * S_LEN * DK];
__device__ __half g_O[(size_t)M_TOT * DM];                // attn out
__device__ float  g_Y[(size_t)M_TOT * DM];                // pre-LN residual sum

// ---------------------------------------------------------------------------
// PTX helpers (all base-target: sm_80+)
// ---------------------------------------------------------------------------
__device__ __forceinline__ void mma_f16(float* c, const uint32_t* a, const uint32_t* b) {
    asm volatile(
        "mma.sync.aligned.m16n8k16.row.col.f32.f16.f16.f32 "
        "{%0,%1,%2,%3}, {%4,%5,%6,%7}, {%8,%9}, {%0,%1,%2,%3};"
        : "+f"(c[0]), "+f"(c[1]), "+f"(c[2]), "+f"(c[3])
        : "r"(a[0]), "r"(a[1]), "r"(a[2]), "r"(a[3]), "r"(b[0]), "r"(b[1]));
}
__device__ __forceinline__ void ldsm4(uint32_t* r, uint32_t addr) {
    asm volatile("ldmatrix.sync.aligned.m8n8.x4.shared.b16 {%0,%1,%2,%3}, [%4];"
                 : "=r"(r[0]), "=r"(r[1]), "=r"(r[2]), "=r"(r[3]) : "r"(addr));
}
__device__ __forceinline__ void ldsm4t(uint32_t* r, uint32_t addr) {
    asm volatile("ldmatrix.sync.aligned.m8n8.x4.trans.shared.b16 {%0,%1,%2,%3}, [%4];"
                 : "=r"(r[0]), "=r"(r[1]), "=r"(r[2]), "=r"(r[3]) : "r"(addr));
}
__device__ __forceinline__ void ldsm2t(uint32_t* r, uint32_t addr) {
    asm volatile("ldmatrix.sync.aligned.m8n8.x2.trans.shared.b16 {%0,%1}, [%2];"
                 : "=r"(r[0]), "=r"(r[1]) : "r"(addr));
}
__device__ __forceinline__ void cp_async16(uint32_t smem_addr, const void* gmem) {
    asm volatile("cp.async.cg.shared.global [%0], [%1], 16;"
                 :: "r"(smem_addr), "l"(gmem));
}
__device__ __forceinline__ void cp_commit() {
    asm volatile("cp.async.commit_group;" ::: "memory");
}
template <int N>
__device__ __forceinline__ void cp_wait() {
    asm volatile("cp.async.wait_group %0;" :: "n"(N) : "memory");
}
__device__ __forceinline__ uint32_t smem_u32(const void* p) {
    uint32_t a;
    asm("{ .reg .u64 t; cvta.to.shared.u64 t, %1; cvt.u32.u64 %0, t; }"
        : "=r"(a) : "l"(p));
    return a;
}
__device__ __forceinline__ uint32_t pack_h2(float lo, float hi) {
    __half2 h = __floats2half2_rn(lo, hi);
    return *reinterpret_cast<uint32_t*>(&h);
}
// 2^x on a packed half2
__device__ __forceinline__ uint32_t h2ex2(uint32_t x) {
    uint32_t y;
    asm("ex2.approx.f16x2 %0, %1;" : "=r"(y) : "r"(x));
    return y;
}

// ---------------------------------------------------------------------------
// fp32 -> fp16 conversions
// ---------------------------------------------------------------------------
__global__ void __launch_bounds__(256) f2h(const float* __restrict__ s,
                                           __half* __restrict__ d)
{
    const size_t i = ((size_t)blockIdx.x * 256 + threadIdx.x) * 8;
    float4 a = *(const float4*)(s + i);
    float4 b = *(const float4*)(s + i + 4);
    __half2* dp = (__half2*)(d + i);
    dp[0] = __floats2half2_rn(a.x, a.y);
    dp[1] = __floats2half2_rn(a.z, a.w);
    dp[2] = __floats2half2_rn(b.x, b.y);
    dp[3] = __floats2half2_rn(b.z, b.w);
}

__global__ void __launch_bounds__(256) w2h(const float* __restrict__ s0,
                                           const float* __restrict__ s1,
                                           const float* __restrict__ s2,
                                           const float* __restrict__ s3)
{
    const float* s = (blockIdx.y == 0) ? s0 : (blockIdx.y == 1) ? s1
                    : (blockIdx.y == 2) ? s2 : s3;
    __half* d = (blockIdx.y == 0) ? g_Wq : (blockIdx.y == 1) ? g_Wk
               : (blockIdx.y == 2) ? g_Wv : g_Wo;
    const size_t i = ((size_t)blockIdx.x * 256 + threadIdx.x) * 8;
    float4 a = *(const float4*)(s + i);
    float4 b = *(const float4*)(s + i + 4);
    __half2* dp = (__half2*)(d + i);
    dp[0] = __floats2half2_rn(a.x, a.y);
    dp[1] = __floats2half2_rn(a.z, a.w);
    dp[2] = __floats2half2_rn(b.x, b.y);
    dp[3] = __floats2half2_rn(b.z, b.w);
}

// ---------------------------------------------------------------------------
// fp16 tensor-core GEMM: C[m][n] = sum_k A[m][k] * W[n][k]   (y = x W^T)
// CTA 256x128, BK=32, 8 warps (4m x 2n), warp tile 64x64, m16n8k16 atoms.
// LDSM/HMMA = 0.25 (vs 0.375 with 64x32 warp tiles) -> smem port no longer
// the binding constraint. 1 CTA/SM (c-frags=128 regs), 3-stage cp.async.
// ---------------------------------------------------------------------------
#define SMH 40
#define STG_A (256 * SMH * 2)          // 20480 B per A stage
#define STG_W (128 * SMH * 2)          // 10240 B per W stage
#define STAGE_B (STG_A + STG_W)        // 30720 B per stage
#define GEMM_SMEM (3 * STAGE_B)        // 92160 B

// Q pre-scale: 1/sqrt(64) * log2(e)  (softmax done in base-2 domain)
#define QSCALE 0.1803368801111f

template <int MODE>
__global__ void __launch_bounds__(256) gemm_h(const float* __restrict__ X32,
                                              const float* __restrict__ bias)
{
    extern __shared__ char smraw[];
    const uint32_t sb = smem_u32(smraw);
    const int tid  = threadIdx.x;
    const int wid  = tid >> 5;
    const int lane = tid & 31;
    const int gid  = lane >> 2;
    const int tig  = lane & 3;
    const int wm   = wid >> 1;       // 0..3  (m warp)
    const int wn   = wid & 1;        // 0..1  (n warp)
    const int m0   = blockIdx.y * 256;
    const int n0   = blockIdx.x * 128;
    const int which = blockIdx.z;

    const __half* Ah = (MODE == 0) ? g_Xh : g_O;
    const __half* Wh = (MODE == 0)
        ? ((which == 0) ? g_Wq : (which == 1) ? g_Wk : g_Wv)
        : g_Wo;

    float c[4][8][4];
#pragma unroll
    for (int mi = 0; mi < 4; mi++)
#pragma unroll
        for (int nj = 0; nj < 8; nj++)
#pragma unroll
            for (int r = 0; r < 4; r++) c[mi][nj][r] = 0.0f;

    // A loader: 256 threads x 1 row (32 halves = 4 cp.async16)
    // W loader: 128 rows, each thread covers 16 halves (2 cp.async16)
    const int warow = tid;                 // 0..255
    const int wrow  = tid >> 1;            // 0..127
    const int wcol  = (tid & 1) << 4;      // 0 or 16 halves

    auto load_tile = [&](int kt) {
        const int st = kt % 3;
        const int kbase = kt << 5;
        const __half* ag = Ah + (size_t)(m0 + warow) * DM + kbase;
        const __half* wg = Wh + (size_t)(n0 + wrow) * DM + kbase + wcol;
        const uint32_t sa = sb + st * STAGE_B + (warow * SMH) * 2;
        const uint32_t sw = sb + st * STAGE_B + STG_A + (wrow * SMH + wcol) * 2;
#pragma unroll
        for (int j = 0; j < 4; j++)
            cp_async16(sa + j * 16, ag + j * 8);
        cp_async16(sw,      wg);
        cp_async16(sw + 16, wg + 8);
        cp_commit();
    };

    load_tile(0);
    load_tile(1);

    // lane-derived LDSM address components
    const int arow   = lane & 15;
    const int achunk = (lane >> 4) << 3;                       // halves
    const int brow   = (lane & 7) + ((lane >> 4) << 3);
    const int bchunk = ((lane >> 3) & 1) << 3;

    for (int kt = 0; kt < 32; ++kt) {
        if (kt == 31) cp_wait<0>(); else cp_wait<1>();
        __syncthreads();
        if (kt + 2 < 32) load_tile(kt + 2);

        const uint32_t stA = sb + (kt % 3) * STAGE_B;
        const uint32_t stB = stA + STG_A;
        const uint32_t aBase = stA + ((wm * 64 + arow) * SMH + achunk) * 2;
        const uint32_t bBase = stB + ((wn * 64 + brow) * SMH + bchunk) * 2;

#pragma unroll
        for (int ka = 0; ka < 2; ka++) {
            uint32_t af[4][4], bf[4][4];
#pragma unroll
            for (int mi = 0; mi < 4; mi++)
                ldsm4(af[mi], aBase + (mi * 16 * SMH + ka * 16) * 2);
#pragma unroll
            for (int nj = 0; nj < 4; nj++)
                ldsm4(bf[nj], bBase + (nj * 16 * SMH + ka * 16) * 2);
#pragma unroll
            for (int mi = 0; mi < 4; mi++)
#pragma unroll
                for (int nj = 0; nj < 4; nj++) {
                    mma_f16(c[mi][2 * nj],     af[mi], bf[nj]);
                    mma_f16(c[mi][2 * nj + 1], af[mi], bf[nj] + 2);
                }
        }
    }

    // Epilogue. c[mi][nj][half*2+r]: row = m0+wm*64+mi*16+gid(+8), col = nj*8+2tig+r
    const float qscale = (MODE == 0 && which == 0) ? QSCALE : 1.0f;
#pragma unroll
    for (int mi = 0; mi < 4; mi++) {
#pragma unroll
        for (int half = 0; half < 2; half++) {
            const int m = m0 + wm * 64 + mi * 16 + gid + half * 8;
#pragma unroll
            for (int nj = 0; nj < 8; nj++) {
                const int n = n0 + wn * 64 + nj * 8 + tig * 2;
                const float v0 = c[mi][nj][half * 2 + 0];
                const float v1 = c[mi][nj][half * 2 + 1];
                if (MODE == 0) {
                    __half* C = (which == 0) ? g_Q : (which == 1) ? g_K : g_V;
                    const int b = m >> 11;
                    const int s = m & (S_LEN - 1);
                    const int h = n >> 6;
                    const int d = n & 63;
                    *(__half2*)(C + (((size_t)(b * NH + h)) * S_LEN + s) * DK + d) =
                        __floats2half2_rn(v0 * qscale, v1 * qscale);
                } else {
                    const float* xp = X32 + (size_t)m * DM + n;
                    float2 o;
                    o.x = v0 + bias[n]     + xp[0];
                    o.y = v1 + bias[n + 1] + xp[1];
                    *(float2*)(g_Y + (size_t)m * DM + n) = o;
                }
            }
        }
    }
}

// ---------------------------------------------------------------------------
// fp16 tensor-core flash attention, FIXED-SHIFT softmax (no max tracking).
// R11 config (best measured): persistent Q frags, full 64-key tiles, double-
// buffered K/V, 1 barrier/iter, prefetch after barrier, 3 CTAs/SM.
// 128 threads (4 warps), 128 q/CTA, 32 q/warp.
// ---------------------------------------------------------------------------
#define AST2 72                               // halves per smem row
#define ATT_TILE_B (64 * AST2 * 2)            // 9216 B per 64x64 K/V tile
#define ATT_Q_B    (128 * AST2 * 2)           // 18432 B
#define ATT_SMEM   (ATT_Q_B + 4 * ATT_TILE_B) // 55296 B

__global__ void __launch_bounds__(128, 3) flash_attn_h()
{
    extern __shared__ char smraw[];
    const uint32_t sb = smem_u32(smraw);
    const uint32_t sQ = sb;
    const uint32_t sK[2] = { sb + ATT_Q_B,
                             sb + ATT_Q_B + 2 * ATT_TILE_B };
    const uint32_t sV[2] = { sb + ATT_Q_B + ATT_TILE_B,
                             sb + ATT_Q_B + 3 * ATT_TILE_B };

    const int tid  = threadIdx.x;
    const int wid  = tid >> 5;
    const int lane = tid & 31;
    const int gid  = lane >> 2;
    const int tig  = lane & 3;
    const int bh   = blockIdx.y;
    const int q0   = blockIdx.x * 128;

    const __half* Qg = g_Q + (size_t)bh * S_LEN * DK;
    const __half* Kg = g_K + (size_t)bh * S_LEN * DK;
    const __half* Vg = g_V + (size_t)bh * S_LEN * DK;

    // K/V loads: 128 threads cover 64 rows x 64 halves per matrix.
    const int kvrow = tid >> 1;            // 0..63
    const int kvcol = (tid & 1) << 5;      // 0 or 32 halves

    auto load_kv = [&](int kt) {
        const int st = kt & 1;
        const size_t gbase = (size_t)(kt * 64 + kvrow) * DK + kvcol;
        const uint32_t sk = sK[st] + (kvrow * AST2 + kvcol) * 2;
        const uint32_t sv = sV[st] + (kvrow * AST2 + kvcol) * 2;
#pragma unroll
        for (int j = 0; j < 4; j++) {
            cp_async16(sk + j * 16, Kg + gbase + j * 8);
            cp_async16(sv + j * 16, Vg + gbase + j * 8);
        }
        cp_commit();
    };

    load_kv(0);

    // Q tile -> smem (128 rows x 64 halves; one row per thread)
    {
        const int qrow = tid;
#pragma unroll
        for (int j = 0; j < 8; j++) {
            *(float4*)(smraw + (qrow * AST2 + j * 8) * 2) =
                *(const float4*)(Qg + (size_t)(q0 + qrow) * DK + j * 8);
        }
    }
    // Init V pad columns of both buffers: col 64 = 1.0 (ones column for row
    // sums), cols 65..71 = 0. cp.async only writes cols 0..63.
    {
        uint4 ones = make_uint4(0x3C00u, 0u, 0u, 0u);
        for (int idx = tid; idx < 2 * 64; idx += 128) {
            const int buf = idx >> 6;
            const int row = idx & 63;
            *(uint4*)(smraw + (ATT_Q_B + (2 * buf + 1) * ATT_TILE_B)
                             + (row * AST2 + 64) * 2) = ones;
        }
    }
    __syncthreads();

    // Persistent Q fragments: warp rows wid*32 + qa*16 + (0..15)
    const int arow   = lane & 15;
    const int achunk = (lane >> 4) << 3;
    uint32_t aq[2][4][4];
#pragma unroll
    for (int qa = 0; qa < 2; qa++)
#pragma unroll
        for (int ka = 0; ka < 4; ka++)
            ldsm4(aq[qa][ka],
                  sQ + ((wid * 32 + qa * 16 + arow) * AST2 + ka * 16 + achunk) * 2);

    float co[2][8][4];
    float co_l[2][4];
#pragma unroll
    for (int qa = 0; qa < 2; qa++) {
#pragma unroll
        for (int ni = 0; ni < 8; ni++)
#pragma unroll
            for (int r = 0; r < 4; r++) co[qa][ni][r] = 0.0f;
#pragma unroll
        for (int r = 0; r < 4; r++) co_l[qa][r] = 0.0f;
    }

    // lane components for K (non-trans) and V (trans) LDSM
    const int krow   = (lane & 7) + ((lane >> 4) << 3);
    const int kchunk = ((lane >> 3) & 1) << 3;
    const int vrow   = (lane & 7) + (((lane >> 3) & 1) << 3);
    const int vchunk = (lane >> 4) << 3;

    for (int kt = 0; kt < 32; ++kt) {
        cp_wait<0>();
        __syncthreads();
        if (kt + 1 < 32) load_kv(kt + 1);   // clobbers buf read in iter kt-1;
                                            // ordered by the barrier above

        const uint32_t bK = sK[kt & 1];
        const uint32_t bV = sV[kt & 1];

        // ---- scores: 32q x 64keys; K fragment reused across both q atoms ----
        float cs[2][8][4];
#pragma unroll
        for (int qa = 0; qa < 2; qa++)
#pragma unroll
            for (int ni = 0; ni < 8; ni++)
#pragma unroll
                for (int r = 0; r < 4; r++) cs[qa][ni][r] = 0.0f;

#pragma unroll
        for (int ka = 0; ka < 4; ka++) {
#pragma unroll
            for (int nip = 0; nip < 4; nip++) {
                uint32_t bf[4];
                ldsm4(bf, bK + ((nip * 16 + krow) * AST2 + ka * 16 + kchunk) * 2);
#pragma unroll
                for (int qa = 0; qa < 2; qa++) {
                    mma_f16(cs[qa][2 * nip],     aq[qa][ka], bf);
                    mma_f16(cs[qa][2 * nip + 1], aq[qa][ka], bf + 2);
                }
            }
        }

        // ---- p = 2^s directly into packed PV A-fragments (no max, no shfl) --
        uint32_t ap[2][4][4];
#pragma unroll
        for (int qa = 0; qa < 2; qa++) {
#pragma unroll
            for (int ka = 0; ka < 4; ka++) {
                ap[qa][ka][0] = h2ex2(pack_h2(cs[qa][2 * ka][0],     cs[qa][2 * ka][1]));
                ap[qa][ka][1] = h2ex2(pack_h2(cs[qa][2 * ka][2],     cs[qa][2 * ka][3]));
                ap[qa][ka][2] = h2ex2(pack_h2(cs[qa][2 * ka + 1][0], cs[qa][2 * ka + 1][1]));
                ap[qa][ka][3] = h2ex2(pack_h2(cs[qa][2 * ka + 1][2], cs[qa][2 * ka + 1][3]));
            }
        }

        // ---- out += P @ V; ones column (64) accumulates row sums ----
#pragma unroll
        for (int ka = 0; ka < 4; ka++) {
#pragma unroll
            for (int nip = 0; nip < 4; nip++) {
                uint32_t bf[4];
                ldsm4t(bf, bV + ((ka * 16 + vrow) * AST2 + nip * 16 + vchunk) * 2);
#pragma unroll
                for (int qa = 0; qa < 2; qa++) {
                    mma_f16(co[qa][2 * nip],     ap[qa][ka], bf);
                    mma_f16(co[qa][2 * nip + 1], ap[qa][ka], bf + 2);
                }
            }
            // l column: cols 64..71 (col 64 = 1.0, rest 0)
            uint32_t bl[2];
            ldsm2t(bl, bV + ((ka * 16 + vrow) * AST2 + 64) * 2);
#pragma unroll
            for (int qa = 0; qa < 2; qa++)
                mma_f16(co_l[qa], ap[qa][ka], bl);
        }
    }

    // ---- epilogue: l lives at col 64 -> lanes with tig==0; broadcast ----
    const int b = bh >> 4;
    const int h = bh & 15;
#pragma unroll
    for (int qa = 0; qa < 2; qa++) {
        const float l0 = __shfl_sync(0xffffffffu, co_l[qa][0], lane & ~3);
        const float l1 = __shfl_sync(0xffffffffu, co_l[qa][2], lane & ~3);
        const float inv0 = 1.0f / l0;
        const float inv1 = 1.0f / l1;
        const int r0 = q0 + wid * 32 + qa * 16 + gid;
        __half* O0 = g_O + (size_t)(b * S_LEN + r0) * DM + h * DK;
        __half* O1 = g_O + (size_t)(b * S_LEN + r0 + 8) * DM + h * DK;
#pragma unroll
        for (int ni = 0; ni < 8; ni++) {
            *(__half2*)(O0 + ni * 8 + 2 * tig) =
                __floats2half2_rn(co[qa][ni][0] * inv0, co[qa][ni][1] * inv0);
            *(__half2*)(O1 + ni * 8 + 2 * tig) =
                __floats2half2_rn(co[qa][ni][2] * inv1, co[qa][ni][3] * inv1);
        }
    }
}

// ---------------------------------------------------------------------------
// LayerNorm over last dim (1024). One block (256 threads) per row.
// ---------------------------------------------------------------------------
__global__ void __launch_bounds__(256) layernorm_k(const float* __restrict__ g,
                                                   const float* __restrict__ be,
                                                   float* __restrict__ out)
{
    const size_t rowbase = (size_t)blockIdx.x * DM;
    const int tid = threadIdx.x;
    const int col = tid << 2;

    float4 v = *(const float4*)(g_Y + rowbase + col);
    float sum = v.x + v.y + v.z + v.w;
    float sq  = v.x * v.x + v.y * v.y + v.z * v.z + v.w * v.w;

#pragma unroll
    for (int off = 16; off > 0; off >>= 1) {
        sum += __shfl_xor_sync(0xffffffffu, sum, off);
        sq  += __shfl_xor_sync(0xffffffffu, sq,  off);
    }
    __shared__ float s1[8], s2[8];
    const int warp = tid >> 5;
    if ((tid & 31) == 0) { s1[warp] = sum; s2[warp] = sq; }
    __syncthreads();
    float tot = 0.0f, totsq = 0.0f;
#pragma unroll
    for (int w = 0; w < 8; w++) { tot += s1[w]; totsq += s2[w]; }

    const float mean = tot * (1.0f / DM);
    const float var  = totsq * (1.0f / DM) - mean * mean;
    const float r    = rsqrtf(var + 1e-5f);

    float4 gg = *(const float4*)(g + col);
    float4 bb = *(const float4*)(be + col);
    float4 o;
    o.x = (v.x - mean) * r * gg.x + bb.x;
    o.y = (v.y - mean) * r * gg.y + bb.y;
    o.z = (v.z - mean) * r * gg.z + bb.z;
    o.w = (v.w - mean) * r * gg.w + bb.w;
    *(float4*)(out + rowbase + col) = o;
}

// ---------------------------------------------------------------------------
// Launcher
// ---------------------------------------------------------------------------
extern "C" void kernel_launch(void* const* d_in, const int* in_sizes, int n_in,
                              void* d_out, int out_size)
{
    const float* x    = (const float*)d_in[0];
    const float* w_q  = (const float*)d_in[1];
    const float* w_k  = (const float*)d_in[2];
    const float* w_v  = (const float*)d_in[3];
    const float* w_o  = (const float*)d_in[4];
    const float* b_o  = (const float*)d_in[5];
    const float* ln_g = (const float*)d_in[6];
    const float* ln_b = (const float*)d_in[7];
    float* out = (float*)d_out;

    __half* xh;
    cudaGetSymbolAddress((void**)&xh, g_Xh);

    cudaFuncSetAttribute(gemm_h<0>, cudaFuncAttributeMaxDynamicSharedMemorySize, GEMM_SMEM);
    cudaFuncSetAttribute(gemm_h<1>, cudaFuncAttributeMaxDynamicSharedMemorySize, GEMM_SMEM);
    cudaFuncSetAttribute(flash_attn_h, cudaFuncAttributeMaxDynamicSharedMemorySize, ATT_SMEM);

    // fp32 -> fp16 conversions
    f2h<<<(M_TOT * DM) / (256 * 8), 256>>>(x, xh);
    dim3 gW((DM * DM) / (256 * 8), 4);
    w2h<<<gW, 256>>>(w_q, w_k, w_v, w_o);

    // Fused Q/K/V projections (CTA tile 256x128)
    dim3 gQKV(DM / 128, M_TOT / 256, 3);   // (8, 32, 3)
    gemm_h<0><<<gQKV, 256, GEMM_SMEM>>>(x, nullptr);

    dim3 gAttn(S_LEN / 128, BATCH * NH);   // (16, 64)
    flash_attn_h<<<gAttn, 128, ATT_SMEM>>>();

    dim3 gO(DM / 128, M_TOT / 256, 1);     // (8, 32)
    gemm_h<1><<<gO, 256, GEMM_SMEM>>>(x, b_o);

    layernorm_k<<<M_TOT, 256>>>(ln_g, ln_b, out);
}

// round 15
// speedup vs baseline: 1.1493x; 1.1493x over previous
#include <cuda_runtime.h>
#include <cuda_fp16.h>
#include <cstdint>

#define BATCH   4
#define S_LEN   2048
#define DM      1024
#define NH      16
#define DK      64
#define M_TOT   (BATCH * S_LEN)   // 8192

// ---------------------------------------------------------------------------
// Scratch (device globals; no dynamic allocation allowed)
// ---------------------------------------------------------------------------
__device__ __half g_Xh[(size_t)M_TOT * DM];
__device__ __half g_Wq[(size_t)DM * DM];
__device__ __half g_Wk[(size_t)DM * DM];
__device__ __half g_Wv[(size_t)DM * DM];
__device__ __half g_Wo[(size_t)DM * DM];
__device__ __half g_Q[(size_t)BATCH * NH * S_LEN * DK];   // [bh, s, d] (scaled by 0.125*log2e)
__device__ __half g_K[(size_t)BATCH * NH * S_LEN * DK];
__device__ __half g_V[(size_t)BATCH * NH * S_LEN * DK];
__device__ __half g_O[(size_t)M_TOT * DM];                // attn out
__device__ float  g_Y[(size_t)M_TOT * DM];                // pre-LN residual sum

// ---------------------------------------------------------------------------
// PTX helpers (all base-target: sm_80+)
// ---------------------------------------------------------------------------
__device__ __forceinline__ void mma_f16(float* c, const uint32_t* a, const uint32_t* b) {
    asm volatile(
        "mma.sync.aligned.m16n8k16.row.col.f32.f16.f16.f32 "
        "{%0,%1,%2,%3}, {%4,%5,%6,%7}, {%8,%9}, {%0,%1,%2,%3};"
        : "+f"(c[0]), "+f"(c[1]), "+f"(c[2]), "+f"(c[3])
        : "r"(a[0]), "r"(a[1]), "r"(a[2]), "r"(a[3]), "r"(b[0]), "r"(b[1]));
}
__device__ __forceinline__ void ldsm4(uint32_t* r, uint32_t addr) {
    asm volatile("ldmatrix.sync.aligned.m8n8.x4.shared.b16 {%0,%1,%2,%3}, [%4];"
                 : "=r"(r[0]), "=r"(r[1]), "=r"(r[2]), "=r"(r[3]) : "r"(addr));
}
__device__ __forceinline__ void ldsm4t(uint32_t* r, uint32_t addr) {
    asm volatile("ldmatrix.sync.aligned.m8n8.x4.trans.shared.b16 {%0,%1,%2,%3}, [%4];"
                 : "=r"(r[0]), "=r"(r[1]), "=r"(r[2]), "=r"(r[3]) : "r"(addr));
}
__device__ __forceinline__ void ldsm2t(uint32_t* r, uint32_t addr) {
    asm volatile("ldmatrix.sync.aligned.m8n8.x2.trans.shared.b16 {%0,%1}, [%2];"
                 : "=r"(r[0]), "=r"(r[1]) : "r"(addr));
}
__device__ __forceinline__ void cp_async16(uint32_t smem_addr, const void* gmem) {
    asm volatile("cp.async.cg.shared.global [%0], [%1], 16;"
                 :: "r"(smem_addr), "l"(gmem));
}
__device__ __forceinline__ void cp_commit() {
    asm volatile("cp.async.commit_group;" ::: "memory");
}
template <int N>
__device__ __forceinline__ void cp_wait() {
    asm volatile("cp.async.wait_group %0;" :: "n"(N) : "memory");
}
__device__ __forceinline__ uint32_t smem_u32(const void* p) {
    uint32_t a;
    asm("{ .reg .u64 t; cvta.to.shared.u64 t, %1; cvt.u32.u64 %0, t; }"
        : "=r"(a) : "l"(p));
    return a;
}
__device__ __forceinline__ uint32_t pack_h2(float lo, float hi) {
    __half2 h = __floats2half2_rn(lo, hi);
    return *reinterpret_cast<uint32_t*>(&h);
}
// 2^x on a packed half2
__device__ __forceinline__ uint32_t h2ex2(uint32_t x) {
    uint32_t y;
    asm("ex2.approx.f16x2 %0, %1;" : "=r"(y) : "r"(x));
    return y;
}

// ---------------------------------------------------------------------------
// fp32 -> fp16 conversions
// ---------------------------------------------------------------------------
__global__ void __launch_bounds__(256) f2h(const float* __restrict__ s,
                                           __half* __restrict__ d)
{
    const size_t i = ((size_t)blockIdx.x * 256 + threadIdx.x) * 8;
    float4 a = *(const float4*)(s + i);
    float4 b = *(const float4*)(s + i + 4);
    __half2* dp = (__half2*)(d + i);
    dp[0] = __floats2half2_rn(a.x, a.y);
    dp[1] = __floats2half2_rn(a.z, a.w);
    dp[2] = __floats2half2_rn(b.x, b.y);
    dp[3] = __floats2half2_rn(b.z, b.w);
}

__global__ void __launch_bounds__(256) w2h(const float* __restrict__ s0,
                                           const float* __restrict__ s1,
                                           const float* __restrict__ s2,
                                           const float* __restrict__ s3)
{
    const float* s = (blockIdx.y == 0) ? s0 : (blockIdx.y == 1) ? s1
                    : (blockIdx.y == 2) ? s2 : s3;
    __half* d = (blockIdx.y == 0) ? g_Wq : (blockIdx.y == 1) ? g_Wk
               : (blockIdx.y == 2) ? g_Wv : g_Wo;
    const size_t i = ((size_t)blockIdx.x * 256 + threadIdx.x) * 8;
    float4 a = *(const float4*)(s + i);
    float4 b = *(const float4*)(s + i + 4);
    __half2* dp = (__half2*)(d + i);
    dp[0] = __floats2half2_rn(a.x, a.y);
    dp[1] = __floats2half2_rn(a.z, a.w);
    dp[2] = __floats2half2_rn(b.x, b.y);
    dp[3] = __floats2half2_rn(b.z, b.w);
}

// ---------------------------------------------------------------------------
// fp16 tensor-core GEMM (R8/R11 config, best measured):
// C[m][n] = sum_k A[m][k] * W[n][k]   (y = x W^T)
// CTA 128x128, BK=32, 8 warps (2m x 4n), warp 64x32, m16n8k16 atoms.
// 3-stage cp.async pipeline; one barrier per k-iter.
// ---------------------------------------------------------------------------
#define SMH 40
#define STG_B (128 * SMH * 2)          // 10240 bytes per matrix per stage
#define STAGE_B (2 * STG_B)            // 20480 bytes per stage
#define GEMM_SMEM (3 * STAGE_B)        // 61440 bytes

// Q pre-scale: 1/sqrt(64) * log2(e)  (softmax done in base-2 domain)
#define QSCALE 0.1803368801111f

template <int MODE>
__global__ void __launch_bounds__(256) gemm_h(const float* __restrict__ X32,
                                              const float* __restrict__ bias)
{
    extern __shared__ char smraw[];
    const uint32_t sb = smem_u32(smraw);
    const int tid  = threadIdx.x;
    const int wid  = tid >> 5;
    const int lane = tid & 31;
    const int gid  = lane >> 2;
    const int tig  = lane & 3;
    const int wm   = wid >> 2;       // 0..1
    const int wn   = wid & 3;        // 0..3
    const int m0   = blockIdx.y * 128;
    const int n0   = blockIdx.x * 128;
    const int which = blockIdx.z;

    const __half* Ah = (MODE == 0) ? g_Xh : g_O;
    const __half* Wh = (MODE == 0)
        ? ((which == 0) ? g_Wq : (which == 1) ? g_Wk : g_Wv)
        : g_Wo;

    const int lrow = tid >> 1;             // 0..127
    const int lcol = (tid & 1) << 4;       // 0 or 16 halves

    float c[4][4][4];
#pragma unroll
    for (int mi = 0; mi < 4; mi++)
#pragma unroll
        for (int ni = 0; ni < 4; ni++)
#pragma unroll
            for (int r = 0; r < 4; r++) c[mi][ni][r] = 0.0f;

    auto load_tile = [&](int kt) {
        const int st = kt % 3;
        const int kbase = kt << 5;
        const __half* ag = Ah + (size_t)(m0 + lrow) * DM + kbase + lcol;
        const __half* wg = Wh + (size_t)(n0 + lrow) * DM + kbase + lcol;
        const uint32_t sa = sb + st * STAGE_B + (lrow * SMH + lcol) * 2;
        const uint32_t sw = sa + STG_B;
        cp_async16(sa,      ag);
        cp_async16(sa + 16, ag + 8);
        cp_async16(sw,      wg);
        cp_async16(sw + 16, wg + 8);
        cp_commit();
    };

    load_tile(0);
    load_tile(1);

    // lane-derived LDSM address components
    const int arow   = lane & 15;
    const int achunk = (lane >> 4) << 3;                       // halves
    const int brow   = (lane & 7) + ((lane >> 4) << 3);
    const int bchunk = ((lane >> 3) & 1) << 3;

    for (int kt = 0; kt < 32; ++kt) {
        if (kt == 31) cp_wait<0>(); else cp_wait<1>();
        __syncthreads();
        if (kt + 2 < 32) load_tile(kt + 2);

        const uint32_t stA = sb + (kt % 3) * STAGE_B;
        const uint32_t stB = stA + STG_B;
        const uint32_t aBase = stA + ((wm * 64 + arow) * SMH + achunk) * 2;
        const uint32_t bBase = stB + ((wn * 32 + brow) * SMH + bchunk) * 2;

#pragma unroll
        for (int ka = 0; ka < 2; ka++) {
            uint32_t af[4][4];
#pragma unroll
            for (int mi = 0; mi < 4; mi++)
                ldsm4(af[mi], aBase + (mi * 16 * SMH + ka * 16) * 2);
#pragma unroll
            for (int nip = 0; nip < 2; nip++) {
                uint32_t bf[4];
                ldsm4(bf, bBase + (nip * 16 * SMH + ka * 16) * 2);
#pragma unroll
                for (int mi = 0; mi < 4; mi++) {
                    mma_f16(c[mi][2 * nip],     af[mi], bf);
                    mma_f16(c[mi][2 * nip + 1], af[mi], bf + 2);
                }
            }
        }
    }

    // Epilogue. c0,c1 = row gid cols 2tig,2tig+1; c2,c3 = row gid+8.
    const float qscale = (MODE == 0 && which == 0) ? QSCALE : 1.0f;
#pragma unroll
    for (int mi = 0; mi < 4; mi++) {
#pragma unroll
        for (int half = 0; half < 2; half++) {
            const int m = m0 + wm * 64 + mi * 16 + gid + half * 8;
#pragma unroll
            for (int ni = 0; ni < 4; ni++) {
                const int n = n0 + wn * 32 + ni * 8 + tig * 2;
                const float v0 = c[mi][ni][half * 2 + 0];
                const float v1 = c[mi][ni][half * 2 + 1];
                if (MODE == 0) {
                    __half* C = (which == 0) ? g_Q : (which == 1) ? g_K : g_V;
                    const int b = m >> 11;
                    const int s = m & (S_LEN - 1);
                    const int h = n >> 6;
                    const int d = n & 63;
                    *(__half2*)(C + (((size_t)(b * NH + h)) * S_LEN + s) * DK + d) =
                        __floats2half2_rn(v0 * qscale, v1 * qscale);
                } else {
                    const float* xp = X32 + (size_t)m * DM + n;
                    float2 o;
                    o.x = v0 + bias[n]     + xp[0];
                    o.y = v1 + bias[n + 1] + xp[1];
                    *(float2*)(g_Y + (size_t)m * DM + n) = o;
                }
            }
        }
    }
}

// ---------------------------------------------------------------------------
// fp16 tensor-core flash attention, FIXED-SHIFT softmax (no max tracking).
// R11 pipeline + two strictly-less-work tweaks:
//  (1) K-phase streamed per 16-key block (nip outer, ka inner): cs shrinks
//      from 64 to 16 live fp32 regs -> scheduling slack under the 170 cap.
//  (2) The ones-column B-fragment (row sums) is CONSTANT across all tiles
//      and buffers -> loaded once before the main loop (removes 4 ldsm2t
//      per warp-iteration).
// 128 threads (4 warps), 128 q/CTA, 32 q/warp, double-buffered K/V, 3 CTAs/SM.
// ---------------------------------------------------------------------------
#define AST2 72                               // halves per smem row
#define ATT_TILE_B (64 * AST2 * 2)            // 9216 B per 64x64 K/V tile
#define ATT_Q_B    (128 * AST2 * 2)           // 18432 B
#define ATT_SMEM   (ATT_Q_B + 4 * ATT_TILE_B) // 55296 B

__global__ void __launch_bounds__(128, 3) flash_attn_h()
{
    extern __shared__ char smraw[];
    const uint32_t sb = smem_u32(smraw);
    const uint32_t sQ = sb;
    const uint32_t sK[2] = { sb + ATT_Q_B,
                             sb + ATT_Q_B + 2 * ATT_TILE_B };
    const uint32_t sV[2] = { sb + ATT_Q_B + ATT_TILE_B,
                             sb + ATT_Q_B + 3 * ATT_TILE_B };

    const int tid  = threadIdx.x;
    const int wid  = tid >> 5;
    const int lane = tid & 31;
    const int gid  = lane >> 2;
    const int tig  = lane & 3;
    const int bh   = blockIdx.y;
    const int q0   = blockIdx.x * 128;

    const __half* Qg = g_Q + (size_t)bh * S_LEN * DK;
    const __half* Kg = g_K + (size_t)bh * S_LEN * DK;
    const __half* Vg = g_V + (size_t)bh * S_LEN * DK;

    // K/V loads: 128 threads cover 64 rows x 64 halves per matrix.
    const int kvrow = tid >> 1;            // 0..63
    const int kvcol = (tid & 1) << 5;      // 0 or 32 halves

    auto load_kv = [&](int kt) {
        const int st = kt & 1;
        const size_t gbase = (size_t)(kt * 64 + kvrow) * DK + kvcol;
        const uint32_t sk = sK[st] + (kvrow * AST2 + kvcol) * 2;
        const uint32_t sv = sV[st] + (kvrow * AST2 + kvcol) * 2;
#pragma unroll
        for (int j = 0; j < 4; j++) {
            cp_async16(sk + j * 16, Kg + gbase + j * 8);
            cp_async16(sv + j * 16, Vg + gbase + j * 8);
        }
        cp_commit();
    };

    load_kv(0);

    // Q tile -> smem (128 rows x 64 halves; one row per thread)
    {
        const int qrow = tid;
#pragma unroll
        for (int j = 0; j < 8; j++) {
            *(float4*)(smraw + (qrow * AST2 + j * 8) * 2) =
                *(const float4*)(Qg + (size_t)(q0 + qrow) * DK + j * 8);
        }
    }
    // Init V pad columns of both buffers: col 64 = 1.0 (ones column for row
    // sums), cols 65..71 = 0. cp.async only writes cols 0..63, so these
    // persist across all iterations.
    {
        uint4 ones = make_uint4(0x3C00u, 0u, 0u, 0u);
        for (int idx = tid; idx < 2 * 64; idx += 128) {
            const int buf = idx >> 6;
            const int row = idx & 63;
            *(uint4*)(smraw + (ATT_Q_B + (2 * buf + 1) * ATT_TILE_B)
                             + (row * AST2 + 64) * 2) = ones;
        }
    }
    __syncthreads();

    // lane components for K (non-trans) and V (trans) LDSM
    const int arow   = lane & 15;
    const int achunk = (lane >> 4) << 3;
    const int krow   = (lane & 7) + ((lane >> 4) << 3);
    const int kchunk = ((lane >> 3) & 1) << 3;
    const int vrow   = (lane & 7) + (((lane >> 3) & 1) << 3);
    const int vchunk = (lane >> 4) << 3;

    // Persistent Q fragments: warp rows wid*32 + qa*16 + (0..15)
    uint32_t aq[2][4][4];
#pragma unroll
    for (int qa = 0; qa < 2; qa++)
#pragma unroll
        for (int ka = 0; ka < 4; ka++)
            ldsm4(aq[qa][ka],
                  sQ + ((wid * 32 + qa * 16 + arow) * AST2 + ka * 16 + achunk) * 2);

    // Constant ones-column B fragment (same values for every tile/buffer):
    // rows vrow (0..15), cols 64..71 of buffer 0's V region.
    uint32_t bl[2];
    ldsm2t(bl, sV[0] + (vrow * AST2 + 64) * 2);

    float co[2][8][4];
    float co_l[2][4];
#pragma unroll
    for (int qa = 0; qa < 2; qa++) {
#pragma unroll
        for (int ni = 0; ni < 8; ni++)
#pragma unroll
            for (int r = 0; r < 4; r++) co[qa][ni][r] = 0.0f;
#pragma unroll
        for (int r = 0; r < 4; r++) co_l[qa][r] = 0.0f;
    }

    for (int kt = 0; kt < 32; ++kt) {
        cp_wait<0>();
        __syncthreads();
        if (kt + 1 < 32) load_kv(kt + 1);   // clobbers buf read in iter kt-1;
                                            // ordered by the barrier above

        const uint32_t bK = sK[kt & 1];
        const uint32_t bV = sV[kt & 1];

        // ---- K-phase streamed per 16-key block: scores -> p -> ap[nip] ----
        uint32_t ap[2][4][4];
#pragma unroll
        for (int nip = 0; nip < 4; nip++) {
            float cs[2][2][4];
#pragma unroll
            for (int qa = 0; qa < 2; qa++)
#pragma unroll
                for (int hb = 0; hb < 2; hb++)
#pragma unroll
                    for (int r = 0; r < 4; r++) cs[qa][hb][r] = 0.0f;

#pragma unroll
            for (int ka = 0; ka < 4; ka++) {
                uint32_t bf[4];
                ldsm4(bf, bK + ((nip * 16 + krow) * AST2 + ka * 16 + kchunk) * 2);
#pragma unroll
                for (int qa = 0; qa < 2; qa++) {
                    mma_f16(cs[qa][0], aq[qa][ka], bf);
                    mma_f16(cs[qa][1], aq[qa][ka], bf + 2);
                }
            }
#pragma unroll
            for (int qa = 0; qa < 2; qa++) {
                ap[qa][nip][0] = h2ex2(pack_h2(cs[qa][0][0], cs[qa][0][1]));
                ap[qa][nip][1] = h2ex2(pack_h2(cs[qa][0][2], cs[qa][0][3]));
                ap[qa][nip][2] = h2ex2(pack_h2(cs[qa][1][0], cs[qa][1][1]));
                ap[qa][nip][3] = h2ex2(pack_h2(cs[qa][1][2], cs[qa][1][3]));
            }
        }

        // ---- out += P @ V; constant ones fragment accumulates row sums ----
#pragma unroll
        for (int ka = 0; ka < 4; ka++) {
#pragma unroll
            for (int nip = 0; nip < 4; nip++) {
                uint32_t bf[4];
                ldsm4t(bf, bV + ((ka * 16 + vrow) * AST2 + nip * 16 + vchunk) * 2);
#pragma unroll
                for (int qa = 0; qa < 2; qa++) {
                    mma_f16(co[qa][2 * nip],     ap[qa][ka], bf);
                    mma_f16(co[qa][2 * nip + 1], ap[qa][ka], bf + 2);
                }
            }
#pragma unroll
            for (int qa = 0; qa < 2; qa++)
                mma_f16(co_l[qa], ap[qa][ka], bl);
        }
    }

    // ---- epilogue: l lives at col 64 -> lanes with tig==0; broadcast ----
    const int b = bh >> 4;
    const int h = bh & 15;
#pragma unroll
    for (int qa = 0; qa < 2; qa++) {
        const float l0 = __shfl_sync(0xffffffffu, co_l[qa][0], lane & ~3);
        const float l1 = __shfl_sync(0xffffffffu, co_l[qa][2], lane & ~3);
        const float inv0 = 1.0f / l0;
        const float inv1 = 1.0f / l1;
        const int r0 = q0 + wid * 32 + qa * 16 + gid;
        __half* O0 = g_O + (size_t)(b * S_LEN + r0) * DM + h * DK;
        __half* O1 = g_O + (size_t)(b * S_LEN + r0 + 8) * DM + h * DK;
#pragma unroll
        for (int ni = 0; ni < 8; ni++) {
            *(__half2*)(O0 + ni * 8 + 2 * tig) =
                __floats2half2_rn(co[qa][ni][0] * inv0, co[qa][ni][1] * inv0);
            *(__half2*)(O1 + ni * 8 + 2 * tig) =
                __floats2half2_rn(co[qa][ni][2] * inv1, co[qa][ni][3] * inv1);
        }
    }
}

// ---------------------------------------------------------------------------
// LayerNorm over last dim (1024). One block (256 threads) per row.
// ---------------------------------------------------------------------------
__global__ void __launch_bounds__(256) layernorm_k(const float* __restrict__ g,
                                                   const float* __restrict__ be,
                                                   float* __restrict__ out)
{
    const size_t rowbase = (size_t)blockIdx.x * DM;
    const int tid = threadIdx.x;
    const int col = tid << 2;

    float4 v = *(const float4*)(g_Y + rowbase + col);
    float sum = v.x + v.y + v.z + v.w;
    float sq  = v.x * v.x + v.y * v.y + v.z * v.z + v.w * v.w;

#pragma unroll
    for (int off = 16; off > 0; off >>= 1) {
        sum += __shfl_xor_sync(0xffffffffu, sum, off);
        sq  += __shfl_xor_sync(0xffffffffu, sq,  off);
    }
    __shared__ float s1[8], s2[8];
    const int warp = tid >> 5;
    if ((tid & 31) == 0) { s1[warp] = sum; s2[warp] = sq; }
    __syncthreads();
    float tot = 0.0f, totsq = 0.0f;
#pragma unroll
    for (int w = 0; w < 8; w++) { tot += s1[w]; totsq += s2[w]; }

    const float mean = tot * (1.0f / DM);
    const float var  = totsq * (1.0f / DM) - mean * mean;
    const float r    = rsqrtf(var + 1e-5f);

    float4 gg = *(const float4*)(g + col);
    float4 bb = *(const float4*)(be + col);
    float4 o;
    o.x = (v.x - mean) * r * gg.x + bb.x;
    o.y = (v.y - mean) * r * gg.y + bb.y;
    o.z = (v.z - mean) * r * gg.z + bb.z;
    o.w = (v.w - mean) * r * gg.w + bb.w;
    *(float4*)(out + rowbase + col) = o;
}

// ---------------------------------------------------------------------------
// Launcher
// ---------------------------------------------------------------------------
extern "C" void kernel_launch(void* const* d_in, const int* in_sizes, int n_in,
                              void* d_out, int out_size)
{
    const float* x    = (const float*)d_in[0];
    const float* w_q  = (const float*)d_in[1];
    const float* w_k  = (const float*)d_in[2];
    const float* w_v  = (const float*)d_in[3];
    const float* w_o  = (const float*)d_in[4];
    const float* b_o  = (const float*)d_in[5];
    const float* ln_g = (const float*)d_in[6];
    const float* ln_b = (const float*)d_in[7];
    float* out = (float*)d_out;

    __half* xh;
    cudaGetSymbolAddress((void**)&xh, g_Xh);

    cudaFuncSetAttribute(gemm_h<0>, cudaFuncAttributeMaxDynamicSharedMemorySize, GEMM_SMEM);
    cudaFuncSetAttribute(gemm_h<1>, cudaFuncAttributeMaxDynamicSharedMemorySize, GEMM_SMEM);
    cudaFuncSetAttribute(flash_attn_h, cudaFuncAttributeMaxDynamicSharedMemorySize, ATT_SMEM);

    // fp32 -> fp16 conversions
    f2h<<<(M_TOT * DM) / (256 * 8), 256>>>(x, xh);
    dim3 gW((DM * DM) / (256 * 8), 4);
    w2h<<<gW, 256>>>(w_q, w_k, w_v, w_o);

    // Fused Q/K/V projections
    dim3 gQKV(DM / 128, M_TOT / 128, 3);   // (8, 64, 3)
    gemm_h<0><<<gQKV, 256, GEMM_SMEM>>>(x, nullptr);

    dim3 gAttn(S_LEN / 128, BATCH * NH);   // (16, 64)
    flash_attn_h<<<gAttn, 128, ATT_SMEM>>>();

    dim3 gO(DM / 128, M_TOT / 128, 1);
    gemm_h<1><<<gO, 256, GEMM_SMEM>>>(x, b_o);

    layernorm_k<<<M_TOT, 256>>>(ln_g, ln_b, out);
}